// round 12
// baseline (speedup 1.0000x reference)
#include <cuda_runtime.h>

// Problem constants (fixed shapes from the reference)
#define T_  1024
#define B_  2
#define N_  10000
#define L_  30
#define S_  61            // 2*L+1

#define NBLK 592          // 148 SMs * 4 -> one wave
#define THR  256
#define WPB  (THR / 32)               // 8 warps per block
#define STRIDE4 (NBLK * THR)          // 151552 float4 grid stride (compile-time)
#define TOTAL4  ((T_ * B_ * N_) / 4)  // 5,120,000 float4
#define NROWS   (B_ * T_)             // 2048 masked rows -> one warp each
#define MASK_BLK (NROWS / WPB)        // 256 masked blocks
#define FULL_ITERS 4                  // 4 x 8 x STRIDE4 = 4,849,664 <= TOTAL4
#define REM_BASE (FULL_ITERS * 8 * STRIDE4)   // leftover 270,336 < 2*STRIDE4

// Scratch (no allocations allowed -> __device__ globals)
__device__ float        g_part[NBLK];
__device__ unsigned int g_count;      // zero-init; advances by exactly NBLK per launch

__device__ __forceinline__ float dot4(const float4 v) {
    return v.x * v.x + v.y * v.y + v.z * v.z + v.w * v.w;
}

// ---------------------------------------------------------------------------
// Single fused kernel:
//  - iteration-0 stream loads issued FIRST; masked prelude (ext/dup/DP) runs
//    under the outstanding LDGs
//  - closed-form lattice: state j active at t <=> d_f[j] <= t && d_b[j] <= T-1-t
//  - 4 x 8 batched LDG.128 + 2 batched predicated remainder loads
//  - warp-per-row masked gather (post-stream, warm L2)
//  - shuffle-based deterministic reductions; last-block finish (ticket mod NBLK)
// ---------------------------------------------------------------------------
__global__ void __launch_bounds__(THR, 4) fused_kernel(const float4* __restrict__ x4,
                                                       const float*  __restrict__ logits,
                                                       const int*    __restrict__ label,
                                                       float* __restrict__ out) {
    const int tid  = threadIdx.x;
    const int lane = tid & 31;
    const int wid  = tid >> 5;
    const bool masked_blk = (blockIdx.x < MASK_BLK);
    const int gid = blockIdx.x * THR + tid;

    __shared__ int                s_ext[S_];
    __shared__ unsigned long long s_dup[S_];
    __shared__ short              s_df[S_], s_db[S_];
    __shared__ float              s_warp[WPB];

    // ---- issue iteration-0 stream loads immediately (prelude hides under them)
    const float4 p0 = x4[gid];
    const float4 p1 = x4[gid +     STRIDE4];
    const float4 p2 = x4[gid + 2 * STRIDE4];
    const float4 p3 = x4[gid + 3 * STRIDE4];
    const float4 p4 = x4[gid + 4 * STRIDE4];
    const float4 p5 = x4[gid + 5 * STRIDE4];
    const float4 p6 = x4[gid + 6 * STRIDE4];
    const float4 p7 = x4[gid + 7 * STRIDE4];

    // --- Phase 0: extended (blank-interleaved) labels ---
    // all 8 rows of a masked block share one batch (1024 rows/batch, 8 rows/block)
    const int bb = (int)((blockIdx.x * WPB) >> 10);
    if (masked_blk && tid < S_)
        s_ext[tid] = (tid & 1) ? label[bb * L_ + (tid >> 1)] : 0;
    __syncthreads();

    // --- Phase 1: dup masks + forward/backward BFS distances (smem-serial) ---
    if (masked_blk) {
        if (tid < S_) {
            const int v = s_ext[tid];
            unsigned long long d = 0ull;
            for (int j2 = 0; j2 < tid; ++j2)
                if (s_ext[j2] == v) d |= 1ull << j2;
            s_dup[tid] = d;
        }
        if (tid == 64) {           // d_f: serial 61-step relaxation (warp 2)
            int dm2 = 0, dm1 = 0;
            s_df[0] = 0; s_df[1] = 0;
            for (int j = 2; j < S_; ++j) {
                int best = dm1;
                if (s_ext[j] != 0 && s_ext[j] != s_ext[j - 2] && dm2 < best) best = dm2;
                const int d = best + 1;
                s_df[j] = (short)d;
                dm2 = dm1; dm1 = d;
            }
        }
        if (tid == 96) {           // d_b: serial 61-step relaxation (warp 3)
            int dp2 = 0, dp1 = 0;
            s_db[S_ - 1] = 0; s_db[S_ - 2] = 0;
            for (int j = S_ - 3; j >= 0; --j) {
                int best = dp1;
                if (s_ext[j] != 0 && s_ext[j] != s_ext[j + 2] && dp2 < best) best = dp2;
                const int d = best + 1;
                s_db[j] = (short)d;
                dp2 = dp1; dp1 = d;
            }
        }
    }

    // ---- consume iteration 0
    float a0 = dot4(p0), a1 = dot4(p1), a2 = dot4(p2), a3 = dot4(p3),
          a4 = dot4(p4), a5 = dot4(p5), a6 = dot4(p6), a7 = dot4(p7);

    // ---- iterations 1..3 (compile-time bounds)
    #pragma unroll 1
    for (int it = 1; it < FULL_ITERS; ++it) {
        const int i = gid + it * (8 * STRIDE4);
        const float4 v0 = x4[i];
        const float4 v1 = x4[i +     STRIDE4];
        const float4 v2 = x4[i + 2 * STRIDE4];
        const float4 v3 = x4[i + 3 * STRIDE4];
        const float4 v4 = x4[i + 4 * STRIDE4];
        const float4 v5 = x4[i + 5 * STRIDE4];
        const float4 v6 = x4[i + 6 * STRIDE4];
        const float4 v7 = x4[i + 7 * STRIDE4];
        a0 += dot4(v0); a1 += dot4(v1); a2 += dot4(v2); a3 += dot4(v3);
        a4 += dot4(v4); a5 += dot4(v5); a6 += dot4(v6); a7 += dot4(v7);
    }
    // ---- remainder: every thread has exactly 1 or 2 elements -> 2 batched loads
    {
        const int r0 = REM_BASE + gid;            // always < TOTAL4
        const int r1 = r0 + STRIDE4;
        const float4 v0 = x4[r0];
        a0 += dot4(v0);
        if (r1 < TOTAL4) {
            const float4 v1 = x4[r1];
            a1 += dot4(v1);
        }
    }
    float acc = (((a0 + a1) + (a2 + a3)) + ((a4 + a5) + (a6 + a7)));

    __syncthreads();   // phase-1 smem writes -> visible to gather readers

    // --- masked rows: warp-per-row gather, lane-parallel states (warm L2) ---
    float neg = 0.0f;
    if (masked_blk) {
        const int gw = blockIdx.x * WPB + wid;   // row id 0..2047
        const int t  = gw & (T_ - 1);
        const int bt = T_ - 1 - t;
        const float* __restrict__ row = logits + (size_t)t * (B_ * N_) + (size_t)bb * N_;

        const int  j1   = lane + 32;
        const bool act0 = (s_df[lane] <= t) && (s_db[lane] <= bt);
        const bool act1 = (j1 < S_) && (s_df[j1] <= t) && (s_db[j1] <= bt);
        const unsigned lo = __ballot_sync(0xFFFFFFFFu, act0);
        const unsigned hi = __ballot_sync(0xFFFFFFFFu, act1);
        const unsigned long long sel =
            (unsigned long long)lo | ((unsigned long long)hi << 32);

        if (act0 && (sel & s_dup[lane]) == 0ull) {
            const float v = __ldg(row + s_ext[lane]);
            neg += v * v;
        }
        if (act1 && (sel & s_dup[j1]) == 0ull) {
            const float v = __ldg(row + s_ext[j1]);
            neg += v * v;
        }
    }

    // --- block reduce: warp shuffle (fixed order) + warp partials in order ---
    float val = acc - neg;
    #pragma unroll
    for (int off = 16; off > 0; off >>= 1)
        val += __shfl_down_sync(0xFFFFFFFFu, val, off);
    if (lane == 0) s_warp[wid] = val;
    __syncthreads();
    if (tid == 0) {
        float s = 0.0f;
        #pragma unroll
        for (int w = 0; w < WPB; ++w) s += s_warp[w];
        g_part[blockIdx.x] = s;
    }

    // --- last-block finish; ticket advances by exactly NBLK per launch ---
    __shared__ bool is_last;
    __threadfence();
    __syncthreads();
    if (tid == 0) {
        const unsigned int ticket = atomicAdd(&g_count, 1u);
        is_last = ((ticket + 1u) % (unsigned)NBLK == 0u);
    }
    __syncthreads();

    if (is_last) {
        // fixed-order accumulation: thread k sums k, k+256, k+512
        float a = 0.0f;
        for (int k = tid; k < NBLK; k += THR) a += g_part[k];
        #pragma unroll
        for (int off = 16; off > 0; off >>= 1)
            a += __shfl_down_sync(0xFFFFFFFFu, a, off);
        if (lane == 0) s_warp[wid] = a;
        __syncthreads();
        if (tid == 0) {
            float s = 0.0f;
            #pragma unroll
            for (int w = 0; w < WPB; ++w) s += s_warp[w];
            out[0] = 0.5f * s;
        }
    }
}

// ---------------------------------------------------------------------------
extern "C" void kernel_launch(void* const* d_in, const int* in_sizes, int n_in,
                              void* d_out, int out_size) {
    // Identify inputs by size (robust to metadata ordering):
    const float* logits = nullptr;
    const int*   label  = nullptr;
    for (int i = 0; i < n_in; ++i) {
        if (in_sizes[i] == T_ * B_ * N_) logits = (const float*)d_in[i];
        else if (in_sizes[i] == B_ * L_) label  = (const int*)d_in[i];
    }
    if (!logits) logits = (const float*)d_in[0];
    if (!label)  label  = (const int*)d_in[2];

    float* out = (float*)d_out;

    fused_kernel<<<NBLK, THR>>>((const float4*)logits, logits, label, out);
}

// round 13
// speedup vs baseline: 1.0953x; 1.0953x over previous
#include <cuda_runtime.h>

// Problem constants (fixed shapes from the reference)
#define T_  1024
#define B_  2
#define N_  10000
#define L_  30
#define S_  61            // 2*L+1

#define NBLK 592          // 148 SMs * 4 -> one wave
#define THR  256
#define WPB  (THR / 32)               // 8 warps per block
#define STRIDE4 (NBLK * THR)          // 151552 float4 grid stride (compile-time)
#define TOTAL4  ((T_ * B_ * N_) / 4)  // 5,120,000 float4
#define NROWS   (B_ * T_)             // 2048 masked rows -> one warp each
#define MASK_BLK (NROWS / WPB)        // 256 masked blocks
#define FULL_ITERS 4                  // 4 x 8 x STRIDE4 = 4,849,664 <= TOTAL4
#define REM_BASE (FULL_ITERS * 8 * STRIDE4)   // leftover 270,336 < 2*STRIDE4

// Scratch (no allocations allowed -> __device__ globals)
__device__ float        g_part[NBLK];
__device__ unsigned int g_count;      // zero-init; advances by exactly NBLK per launch

__device__ __forceinline__ float dot4(const float4 v) {
    return v.x * v.x + v.y * v.y + v.z * v.z + v.w * v.w;
}

// ---------------------------------------------------------------------------
// Single fused kernel (R10 loop structure + smem DP + shuffle reductions):
//  - masked prelude: ext labels, dup masks, lattice BFS distances (smem-serial)
//    closed form: state j active at t <=> d_f[j] <= t && d_b[j] <= T-1-t
//  - 4 x 8 batched LDG.128 (loads consumed in-iteration; no cross-barrier
//    register pressure) + 2 batched predicated remainder loads
//  - warp-per-row masked gather (post-stream, warm L2)
//  - shuffle-based deterministic reductions; last-block finish (ticket mod NBLK)
// ---------------------------------------------------------------------------
__global__ void __launch_bounds__(THR, 4) fused_kernel(const float4* __restrict__ x4,
                                                       const float*  __restrict__ logits,
                                                       const int*    __restrict__ label,
                                                       float* __restrict__ out) {
    const int tid  = threadIdx.x;
    const int lane = tid & 31;
    const int wid  = tid >> 5;
    const bool masked_blk = (blockIdx.x < MASK_BLK);
    const int gid = blockIdx.x * THR + tid;

    __shared__ int                s_ext[S_];
    __shared__ unsigned long long s_dup[S_];
    __shared__ short              s_df[S_], s_db[S_];
    __shared__ float              s_warp[WPB];

    // --- Phase 0: extended (blank-interleaved) labels ---
    // all 8 rows of a masked block share one batch (1024 rows/batch, 8 rows/block)
    const int bb = (int)((blockIdx.x * WPB) >> 10);
    if (masked_blk && tid < S_)
        s_ext[tid] = (tid & 1) ? label[bb * L_ + (tid >> 1)] : 0;
    __syncthreads();

    // --- Phase 1: dup masks + forward/backward BFS distances (smem-serial) ---
    if (masked_blk) {
        if (tid < S_) {
            const int v = s_ext[tid];
            unsigned long long d = 0ull;
            for (int j2 = 0; j2 < tid; ++j2)
                if (s_ext[j2] == v) d |= 1ull << j2;
            s_dup[tid] = d;
        }
        if (tid == 64) {           // d_f: serial 61-step relaxation (warp 2)
            int dm2 = 0, dm1 = 0;
            s_df[0] = 0; s_df[1] = 0;
            for (int j = 2; j < S_; ++j) {
                int best = dm1;
                if (s_ext[j] != 0 && s_ext[j] != s_ext[j - 2] && dm2 < best) best = dm2;
                const int d = best + 1;
                s_df[j] = (short)d;
                dm2 = dm1; dm1 = d;
            }
        }
        if (tid == 96) {           // d_b: serial 61-step relaxation (warp 3)
            int dp2 = 0, dp1 = 0;
            s_db[S_ - 1] = 0; s_db[S_ - 2] = 0;
            for (int j = S_ - 3; j >= 0; --j) {
                int best = dp1;
                if (s_ext[j] != 0 && s_ext[j] != s_ext[j + 2] && dp2 < best) best = dp2;
                const int d = best + 1;
                s_db[j] = (short)d;
                dp2 = dp1; dp1 = d;
            }
        }
    }

    // --- full sum of squares: 4 x (8 batched LDG.128), compile-time bounds ---
    float a0 = 0.f, a1 = 0.f, a2 = 0.f, a3 = 0.f,
          a4 = 0.f, a5 = 0.f, a6 = 0.f, a7 = 0.f;
    #pragma unroll 1
    for (int it = 0; it < FULL_ITERS; ++it) {
        const int i = gid + it * (8 * STRIDE4);
        const float4 v0 = x4[i];
        const float4 v1 = x4[i +     STRIDE4];
        const float4 v2 = x4[i + 2 * STRIDE4];
        const float4 v3 = x4[i + 3 * STRIDE4];
        const float4 v4 = x4[i + 4 * STRIDE4];
        const float4 v5 = x4[i + 5 * STRIDE4];
        const float4 v6 = x4[i + 6 * STRIDE4];
        const float4 v7 = x4[i + 7 * STRIDE4];
        a0 += dot4(v0); a1 += dot4(v1); a2 += dot4(v2); a3 += dot4(v3);
        a4 += dot4(v4); a5 += dot4(v5); a6 += dot4(v6); a7 += dot4(v7);
    }
    // remainder: every thread has exactly 1 or 2 elements -> 2 batched loads
    {
        const int r0 = REM_BASE + gid;            // always < TOTAL4
        const int r1 = r0 + STRIDE4;
        const float4 v0 = x4[r0];
        a0 += dot4(v0);
        if (r1 < TOTAL4) {
            const float4 v1 = x4[r1];
            a1 += dot4(v1);
        }
    }
    float acc = (((a0 + a1) + (a2 + a3)) + ((a4 + a5) + (a6 + a7)));

    __syncthreads();   // phase-1 smem writes -> visible to gather readers

    // --- masked rows: warp-per-row gather, lane-parallel states (warm L2) ---
    float neg = 0.0f;
    if (masked_blk) {
        const int gw = blockIdx.x * WPB + wid;   // row id 0..2047
        const int t  = gw & (T_ - 1);
        const int bt = T_ - 1 - t;
        const float* __restrict__ row = logits + (size_t)t * (B_ * N_) + (size_t)bb * N_;

        const int  j1   = lane + 32;
        const bool act0 = (s_df[lane] <= t) && (s_db[lane] <= bt);
        const bool act1 = (j1 < S_) && (s_df[j1] <= t) && (s_db[j1] <= bt);
        const unsigned lo = __ballot_sync(0xFFFFFFFFu, act0);
        const unsigned hi = __ballot_sync(0xFFFFFFFFu, act1);
        const unsigned long long sel =
            (unsigned long long)lo | ((unsigned long long)hi << 32);

        if (act0 && (sel & s_dup[lane]) == 0ull) {
            const float v = __ldg(row + s_ext[lane]);
            neg += v * v;
        }
        if (act1 && (sel & s_dup[j1]) == 0ull) {
            const float v = __ldg(row + s_ext[j1]);
            neg += v * v;
        }
    }

    // --- block reduce: warp shuffle (fixed order) + warp partials in order ---
    float val = acc - neg;
    #pragma unroll
    for (int off = 16; off > 0; off >>= 1)
        val += __shfl_down_sync(0xFFFFFFFFu, val, off);
    if (lane == 0) s_warp[wid] = val;
    __syncthreads();
    if (tid == 0) {
        float s = 0.0f;
        #pragma unroll
        for (int w = 0; w < WPB; ++w) s += s_warp[w];
        g_part[blockIdx.x] = s;
    }

    // --- last-block finish; ticket advances by exactly NBLK per launch ---
    __shared__ bool is_last;
    __threadfence();
    __syncthreads();
    if (tid == 0) {
        const unsigned int ticket = atomicAdd(&g_count, 1u);
        is_last = ((ticket + 1u) % (unsigned)NBLK == 0u);
    }
    __syncthreads();

    if (is_last) {
        // fixed-order accumulation: thread k sums k, k+256, k+512
        float a = 0.0f;
        for (int k = tid; k < NBLK; k += THR) a += g_part[k];
        #pragma unroll
        for (int off = 16; off > 0; off >>= 1)
            a += __shfl_down_sync(0xFFFFFFFFu, a, off);
        if (lane == 0) s_warp[wid] = a;
        __syncthreads();
        if (tid == 0) {
            float s = 0.0f;
            #pragma unroll
            for (int w = 0; w < WPB; ++w) s += s_warp[w];
            out[0] = 0.5f * s;
        }
    }
}

// ---------------------------------------------------------------------------
extern "C" void kernel_launch(void* const* d_in, const int* in_sizes, int n_in,
                              void* d_out, int out_size) {
    // Identify inputs by size (robust to metadata ordering):
    const float* logits = nullptr;
    const int*   label  = nullptr;
    for (int i = 0; i < n_in; ++i) {
        if (in_sizes[i] == T_ * B_ * N_) logits = (const float*)d_in[i];
        else if (in_sizes[i] == B_ * L_) label  = (const int*)d_in[i];
    }
    if (!logits) logits = (const float*)d_in[0];
    if (!label)  label  = (const int*)d_in[2];

    float* out = (float*)d_out;

    fused_kernel<<<NBLK, THR>>>((const float4*)logits, logits, label, out);
}